// round 1
// baseline (speedup 1.0000x reference)
#include <cuda_runtime.h>
#include <cstdint>

// Problem shape (fixed by the dataset): B=2, S=2048, A=16, H=1024, NH=16, HD=64
#define BB 2
#define SS 2048
#define AA 16
#define HH 1024
#define NH 16
#define HD 64

// ---- scratch (device globals; no allocation allowed) ----
__device__ __align__(16) float g_q[BB * HH];          // q[b, o]
__device__ __align__(16) float g_v[BB * NH * HH];     // v[b, h, i]
__device__ __align__(16) float g_scores[BB * NH * SS];// s[b, h, k]
__device__ __align__(16) float g_w[BB * SS];          // final per-key weights

// ---- mask dtype detection ----
// First 4 entries of sentence_mask[0] are always true (sent_len >= S/2 >= 4),
// so word0 uniquely identifies the storage format.
__device__ __forceinline__ int detect_mode(const void* sm) {
    unsigned int w0 = *(const unsigned int*)sm;
    if (w0 == 0x01010101u) return 1;   // 1-byte bool
    if (w0 == 0x3F800000u) return 2;   // float32
    if (w0 == 0x3F803F80u) return 3;   // bf16
    return 0;                          // int32
}
__device__ __forceinline__ bool mask_at(const void* p, int idx, int mode) {
    switch (mode) {
        case 1:  return ((const unsigned char*)p)[idx] != 0;
        case 2:  return ((const float*)p)[idx] != 0.0f;
        case 3:  return ((const unsigned short*)p)[idx] != 0;
        default: return ((const int*)p)[idx] != 0;
    }
}

// ---- Kernel 1: masked mean of h2 over aspects, then q[b,o] = dot(Wq[o,:], agg) ----
// grid (B, H/8), block 256 (8 warps), one warp per output row o.
__global__ void k_agg_q(const float* __restrict__ h2, const void* __restrict__ am,
                        const void* __restrict__ sm, const float* __restrict__ Wq) {
    int b = blockIdx.x;
    int mode = detect_mode(sm);
    __shared__ float agg[HH];
    int t = threadIdx.x;

    float cnt = 0.f;
#pragma unroll
    for (int a = 0; a < AA; a++) cnt += mask_at(am, b * AA + a, mode) ? 1.f : 0.f;
    float inv = 1.f / fmaxf(cnt, 1.f);

    for (int i = t; i < HH; i += 256) {
        float s = 0.f;
#pragma unroll
        for (int a = 0; a < AA; a++)
            if (mask_at(am, b * AA + a, mode)) s += h2[(b * AA + a) * HH + i];
        agg[i] = s * inv;
    }
    __syncthreads();

    int warp = t >> 5, lane = t & 31;
    int o = blockIdx.y * 8 + warp;
    const float* wrow = Wq + (size_t)o * HH;
    float acc = 0.f;
    for (int i = lane; i < HH; i += 32) acc += wrow[i] * agg[i];
#pragma unroll
    for (int off = 16; off; off >>= 1) acc += __shfl_xor_sync(0xffffffffu, acc, off);
    if (lane == 0) g_q[b * HH + o] = acc;
}

// ---- Kernel 2: fold q into Wk per head: v[b,h,i] = sum_{o in head h} q[b,h*64+o] * Wk[h*64+o, i] ----
// grid (B, H/128), block 128; thread handles one column i for all heads.
__global__ void k_fold_v(const float* __restrict__ Wk) {
    int b = blockIdx.x;
    int i = blockIdx.y * 128 + threadIdx.x;
    __shared__ float qsh[HH];
    for (int j = threadIdx.x; j < HH; j += 128) qsh[j] = g_q[b * HH + j];
    __syncthreads();

#pragma unroll
    for (int h = 0; h < NH; h++) {
        float acc = 0.f;
#pragma unroll
        for (int o = 0; o < HD; o++)
            acc += qsh[h * HD + o] * Wk[(size_t)(h * HD + o) * HH + i];
        g_v[(b * NH + h) * HH + i] = acc;
    }
}

// ---- Kernel 3: scores[b,h,k] = scale * dot(v[b,h,:], h1[b,k,:]) ----
// grid (B, 64): block covers 32 k's; 8 warps x KT=4 k per warp (register tiled),
// v[b] staged in 64KB dynamic smem (one LDS feeds 4 FMAs).
#define KT 4
extern __shared__ float vsh[];
__global__ void k_scores(const float* __restrict__ h1) {
    int b = blockIdx.x;
    int t = threadIdx.x;
    const float4* vb = (const float4*)(g_v + (size_t)b * NH * HH);
    float4* vs4 = (float4*)vsh;
    for (int j = t; j < NH * HH / 4; j += 256) vs4[j] = vb[j];
    __syncthreads();

    int warp = t >> 5, lane = t & 31;
    int k0 = blockIdx.y * 32 + warp * KT;
    const float scale = 0.125f;  // 1/sqrt(64)

    const float* r0 = h1 + (size_t)(b * SS + k0 + 0) * HH;
    const float* r1 = h1 + (size_t)(b * SS + k0 + 1) * HH;
    const float* r2 = h1 + (size_t)(b * SS + k0 + 2) * HH;
    const float* r3 = h1 + (size_t)(b * SS + k0 + 3) * HH;

    float acc[NH][KT];
#pragma unroll
    for (int h = 0; h < NH; h++)
#pragma unroll
        for (int j = 0; j < KT; j++) acc[h][j] = 0.f;

    for (int m = 0; m < HH / 32; m++) {
        int i = lane + m * 32;
        float x0 = r0[i], x1 = r1[i], x2 = r2[i], x3 = r3[i];
#pragma unroll
        for (int h = 0; h < NH; h++) {
            float v = vsh[h * HH + i];
            acc[h][0] += v * x0;
            acc[h][1] += v * x1;
            acc[h][2] += v * x2;
            acc[h][3] += v * x3;
        }
    }
#pragma unroll
    for (int h = 0; h < NH; h++) {
#pragma unroll
        for (int j = 0; j < KT; j++) {
            float s = acc[h][j];
#pragma unroll
            for (int off = 16; off; off >>= 1) s += __shfl_xor_sync(0xffffffffu, s, off);
            acc[h][j] = s;  // every lane now holds the full sum
        }
    }
    if (lane < NH) {
        int h = lane;
#pragma unroll
        for (int j = 0; j < KT; j++)
            g_scores[(size_t)(b * NH + h) * SS + k0 + j] = acc[h][j] * scale;
    }
}

// ---- Kernel 4: masked softmax over k per (b,h), then mean over heads -> w[b,k] ----
// grid B, block 512 (16 warps; warp == head).
__global__ void k_softmax(const void* __restrict__ sm) {
    int b = blockIdx.x;
    int mode = detect_mode(sm);
    int t = threadIdx.x;
    int warp = t >> 5, lane = t & 31;
    __shared__ float sh_m[NH], sh_iz[NH];

    const float* srow = g_scores + (size_t)(b * NH + warp) * SS;
    float mx = -1e30f;
    for (int k = lane; k < SS; k += 32)
        if (mask_at(sm, b * SS + k, mode)) mx = fmaxf(mx, srow[k]);
#pragma unroll
    for (int off = 16; off; off >>= 1) mx = fmaxf(mx, __shfl_xor_sync(0xffffffffu, mx, off));
    float z = 0.f;
    for (int k = lane; k < SS; k += 32)
        if (mask_at(sm, b * SS + k, mode)) z += __expf(srow[k] - mx);
#pragma unroll
    for (int off = 16; off; off >>= 1) z += __shfl_xor_sync(0xffffffffu, z, off);
    if (lane == 0) { sh_m[warp] = mx; sh_iz[warp] = 1.f / z; }
    __syncthreads();

    float lm[NH], liz[NH];
#pragma unroll
    for (int h = 0; h < NH; h++) { lm[h] = sh_m[h]; liz[h] = sh_iz[h]; }

    for (int k = t; k < SS; k += 512) {
        float wv = 0.f;
        if (mask_at(sm, b * SS + k, mode)) {
#pragma unroll
            for (int h = 0; h < NH; h++)
                wv += __expf(g_scores[(size_t)(b * NH + h) * SS + k] - lm[h]) * liz[h];
            wv *= (1.0f / NH);
        }
        g_w[b * SS + k] = wv;
    }
}

// ---- Kernel 5: broadcast w[b,:] to all S query rows of the output ----
// grid B*S (one block per output row), block 512, float4 stores.
__global__ void k_bcast(float* __restrict__ out) {
    int row = blockIdx.x;           // b*S + q
    int b = row >> 11;              // / 2048
    float4 v = ((const float4*)(g_w + b * SS))[threadIdx.x];
    ((float4*)(out + (size_t)row * SS))[threadIdx.x] = v;
}

extern "C" void kernel_launch(void* const* d_in, const int* in_sizes, int n_in,
                              void* d_out, int out_size) {
    const float* h1 = (const float*)d_in[0];   // [B,S,H]
    const float* h2 = (const float*)d_in[1];   // [B,A,H]
    const void*  sm = d_in[2];                 // [B,S] bool-ish
    const void*  am = d_in[3];                 // [B,A] bool-ish
    const float* Wq = (const float*)d_in[4];   // [H,H]
    const float* Wk = (const float*)d_in[5];   // [H,H]
    float* out = (float*)d_out;                // [B,S,S]

    k_agg_q<<<dim3(BB, HH / 8), 256>>>(h2, am, sm, Wq);
    k_fold_v<<<dim3(BB, HH / 128), 128>>>(Wk);

    static int smem_set = 0;
    (void)smem_set;
    cudaFuncSetAttribute(k_scores, cudaFuncAttributeMaxDynamicSharedMemorySize,
                         NH * HH * (int)sizeof(float));
    k_scores<<<dim3(BB, 64), 256, NH * HH * sizeof(float)>>>(h1);

    k_softmax<<<BB, 512>>>(sm);
    k_bcast<<<BB * SS, 512>>>(out);
}

// round 2
// speedup vs baseline: 1.6149x; 1.6149x over previous
#include <cuda_runtime.h>
#include <cstdint>

// Problem shape (fixed by dataset): B=2, S=2048, A=16, H=1024, NH=16, HD=64
#define BB 2
#define SS 2048
#define AA 16
#define HH 1024
#define NH 16
#define HD 64

// ---- scratch (device globals; no allocation allowed) ----
__device__ __align__(16) float g_agg[BB * HH];         // masked-mean aspect features
__device__ __align__(16) float g_q[BB * HH];           // q[b, o]
__device__ __align__(16) float g_v[BB * NH * HH];      // folded key weights v[b, h, i]
__device__ __align__(16) float g_scores[BB * NH * SS]; // s[b, h, k]
__device__ __align__(16) float g_m[BB * NH];           // per-(b,h) max
__device__ __align__(16) float g_iz[BB * NH];          // per-(b,h) 1/(z*NH)
__device__ __align__(16) float g_w[BB * SS];           // final per-key weights

// ---- mask dtype detection (sentence_mask[0][0..3] always true since len >= S/2) ----
__device__ __forceinline__ int detect_mode(const void* sm) {
    unsigned int w0 = *(const unsigned int*)sm;
    if (w0 == 0x01010101u) return 1;   // 1-byte bool
    if (w0 == 0x3F800000u) return 2;   // float32
    if (w0 == 0x3F803F80u) return 3;   // bf16
    return 0;                          // int32
}
__device__ __forceinline__ bool mask_at(const void* p, int idx, int mode) {
    switch (mode) {
        case 1:  return ((const unsigned char*)p)[idx] != 0;
        case 2:  return ((const float*)p)[idx] != 0.0f;
        case 3:  return ((const unsigned short*)p)[idx] != 0;
        default: return ((const int*)p)[idx] != 0;
    }
}

// ---- K1: masked mean over aspects -> g_agg[b][i].  grid BB, block 256. ----
__global__ void k_agg(const float* __restrict__ h2, const void* __restrict__ am,
                      const void* __restrict__ sm) {
    int b = blockIdx.x;
    int mode = detect_mode(sm);
    float cnt = 0.f;
#pragma unroll
    for (int a = 0; a < AA; a++) cnt += mask_at(am, b * AA + a, mode) ? 1.f : 0.f;
    float inv = 1.f / fmaxf(cnt, 1.f);
    for (int i = threadIdx.x; i < HH; i += 256) {
        float s = 0.f;
#pragma unroll
        for (int a = 0; a < AA; a++)
            if (mask_at(am, b * AA + a, mode)) s += h2[(b * AA + a) * HH + i];
        g_agg[b * HH + i] = s * inv;
    }
}

// ---- K2: q[b,o] = dot(Wq[o,:], agg[b]).  grid (BB, HH/8), 8 warps, warp-per-row. ----
__global__ void __launch_bounds__(256) k_q(const float* __restrict__ Wq) {
    int b = blockIdx.x;
    int warp = threadIdx.x >> 5, lane = threadIdx.x & 31;
    int o = blockIdx.y * 8 + warp;
    const float4* wrow = (const float4*)(Wq + (size_t)o * HH);
    const float4* ag = (const float4*)(g_agg + b * HH);
    float acc = 0.f;
#pragma unroll
    for (int j = 0; j < HH / 128; j++) {   // 8 float4 per lane
        float4 wv = wrow[lane + j * 32];
        float4 av = ag[lane + j * 32];
        acc += wv.x * av.x + wv.y * av.y + wv.z * av.z + wv.w * av.w;
    }
#pragma unroll
    for (int off = 16; off; off >>= 1) acc += __shfl_xor_sync(0xffffffffu, acc, off);
    if (lane == 0) g_q[b * HH + o] = acc;
}

// ---- K3: v[b,h,i] = sum_o q[b,h*64+o] * Wk[h*64+o, i].  grid (BB*NH, HH/256), 256 thr. ----
__global__ void __launch_bounds__(256) k_fold(const float* __restrict__ Wk) {
    int b = blockIdx.x >> 4;
    int h = blockIdx.x & 15;
    int i = blockIdx.y * 256 + threadIdx.x;
    __shared__ float qs[HD];
    if (threadIdx.x < HD) qs[threadIdx.x] = g_q[b * HH + h * HD + threadIdx.x];
    __syncthreads();
    float acc = 0.f;
#pragma unroll 8
    for (int o = 0; o < HD; o++)
        acc += qs[o] * Wk[(size_t)(h * HD + o) * HH + i];
    g_v[(b * NH + h) * HH + i] = acc;
}

// ---- K4: scores[b,h,k] = 0.125 * dot(v[b,h,:], h1[b,k,:]) ----
// grid (BB, 64): 8 warps x KT=4 k per warp; v staged in 64KB smem; float4 everywhere.
#define KT 4
extern __shared__ float vsh[];
__global__ void __launch_bounds__(256) k_scores(const float* __restrict__ h1) {
    int b = blockIdx.x;
    int t = threadIdx.x;
    const float4* vb = (const float4*)(g_v + (size_t)b * NH * HH);
    float4* vs4 = (float4*)vsh;
    for (int j = t; j < NH * HH / 4; j += 256) vs4[j] = vb[j];
    __syncthreads();

    int warp = t >> 5, lane = t & 31;
    int k0 = blockIdx.y * 32 + warp * KT;

    const float4* r0 = (const float4*)(h1 + (size_t)(b * SS + k0 + 0) * HH);
    const float4* r1 = (const float4*)(h1 + (size_t)(b * SS + k0 + 1) * HH);
    const float4* r2 = (const float4*)(h1 + (size_t)(b * SS + k0 + 2) * HH);
    const float4* r3 = (const float4*)(h1 + (size_t)(b * SS + k0 + 3) * HH);

    float acc[NH][KT];
#pragma unroll
    for (int h = 0; h < NH; h++)
#pragma unroll
        for (int j = 0; j < KT; j++) acc[h][j] = 0.f;

#pragma unroll
    for (int m = 0; m < HH / 128; m++) {   // 8 iterations, 128 i's each
        int idx = lane + m * 32;
        float4 x0 = r0[idx], x1 = r1[idx], x2 = r2[idx], x3 = r3[idx];
#pragma unroll
        for (int h = 0; h < NH; h++) {
            float4 v = vs4[h * (HH / 4) + idx];
            acc[h][0] += v.x * x0.x + v.y * x0.y + v.z * x0.z + v.w * x0.w;
            acc[h][1] += v.x * x1.x + v.y * x1.y + v.z * x1.z + v.w * x1.w;
            acc[h][2] += v.x * x2.x + v.y * x2.y + v.z * x2.z + v.w * x2.w;
            acc[h][3] += v.x * x3.x + v.y * x3.y + v.z * x3.z + v.w * x3.w;
        }
    }
#pragma unroll
    for (int h = 0; h < NH; h++)
#pragma unroll
        for (int j = 0; j < KT; j++) {
            float s = acc[h][j];
#pragma unroll
            for (int off = 16; off; off >>= 1) s += __shfl_xor_sync(0xffffffffu, s, off);
            acc[h][j] = s;
        }
    if (lane < NH) {
        int h = lane;
#pragma unroll
        for (int j = 0; j < KT; j++)
            g_scores[(size_t)(b * NH + h) * SS + k0 + j] = acc[h][j] * 0.125f;
    }
}

// ---- K5: per-(b,h) masked max + sum-of-exp.  grid BB*NH, block 256. ----
__global__ void __launch_bounds__(256) k_reduce(const void* __restrict__ sm) {
    int b = blockIdx.x >> 4;
    int h = blockIdx.x & 15;
    int mode = detect_mode(sm);
    int t = threadIdx.x, warp = t >> 5, lane = t & 31;
    const float* srow = g_scores + (size_t)(b * NH + h) * SS;
    __shared__ float red[8];

    float mx = -1e30f;
    for (int k = t; k < SS; k += 256)
        if (mask_at(sm, b * SS + k, mode)) mx = fmaxf(mx, srow[k]);
#pragma unroll
    for (int off = 16; off; off >>= 1) mx = fmaxf(mx, __shfl_xor_sync(0xffffffffu, mx, off));
    if (lane == 0) red[warp] = mx;
    __syncthreads();
    mx = red[lane & 7];
#pragma unroll
    for (int off = 4; off; off >>= 1) mx = fmaxf(mx, __shfl_xor_sync(0xffffffffu, mx, off));
    // all lanes of warp now hold block max (values replicated); broadcast via shfl idx 0 safe
    mx = __shfl_sync(0xffffffffu, mx, 0);
    __syncthreads();

    float z = 0.f;
    for (int k = t; k < SS; k += 256)
        if (mask_at(sm, b * SS + k, mode)) z += __expf(srow[k] - mx);
#pragma unroll
    for (int off = 16; off; off >>= 1) z += __shfl_xor_sync(0xffffffffu, z, off);
    if (lane == 0) red[warp] = z;
    __syncthreads();
    if (t == 0) {
        float zz = 0.f;
#pragma unroll
        for (int wj = 0; wj < 8; wj++) zz += red[wj];
        g_m[b * NH + h] = mx;
        g_iz[b * NH + h] = 1.f / (zz * (float)NH);
    }
}

// ---- K6: w[b,k] = sum_h exp(s[b,h,k]-m[b,h]) * iz[b,h]  (0 if masked out). grid 8, 512 thr. ----
__global__ void __launch_bounds__(512) k_w(const void* __restrict__ sm) {
    int gid = blockIdx.x * 512 + threadIdx.x;   // 0 .. B*S-1
    int b = gid >> 11;
    int k = gid & (SS - 1);
    int mode = detect_mode(sm);
    float wv = 0.f;
    if (mask_at(sm, b * SS + k, mode)) {
#pragma unroll
        for (int h = 0; h < NH; h++) {
            float s = g_scores[(size_t)(b * NH + h) * SS + k];
            wv += __expf(s - g_m[b * NH + h]) * g_iz[b * NH + h];
        }
    }
    g_w[gid] = wv;
}

// ---- K7: broadcast w[b,:] to all S query rows.  grid B*S, 512 thr, float4. ----
__global__ void __launch_bounds__(512) k_bcast(float* __restrict__ out) {
    int row = blockIdx.x;          // b*S + q
    int b = row >> 11;
    float4 v = ((const float4*)(g_w + b * SS))[threadIdx.x];
    ((float4*)(out + (size_t)row * SS))[threadIdx.x] = v;
}

extern "C" void kernel_launch(void* const* d_in, const int* in_sizes, int n_in,
                              void* d_out, int out_size) {
    const float* h1 = (const float*)d_in[0];   // [B,S,H]
    const float* h2 = (const float*)d_in[1];   // [B,A,H]
    const void*  sm = d_in[2];                 // [B,S]
    const void*  am = d_in[3];                 // [B,A]
    const float* Wq = (const float*)d_in[4];   // [H,H]
    const float* Wk = (const float*)d_in[5];   // [H,H]
    float* out = (float*)d_out;                // [B,S,S]

    k_agg<<<BB, 256>>>(h2, am, sm);
    k_q<<<dim3(BB, HH / 8), 256>>>(Wq);
    k_fold<<<dim3(BB * NH, HH / 256), 256>>>(Wk);

    cudaFuncSetAttribute(k_scores, cudaFuncAttributeMaxDynamicSharedMemorySize,
                         NH * HH * (int)sizeof(float));
    k_scores<<<dim3(BB, 64), 256, NH * HH * sizeof(float)>>>(h1);

    k_reduce<<<BB * NH, 256>>>(sm);
    k_w<<<(BB * SS) / 512, 512>>>(sm);
    k_bcast<<<BB * SS, 512>>>(out);
}

// round 3
// speedup vs baseline: 1.6372x; 1.0138x over previous
#include <cuda_runtime.h>
#include <cstdint>

// Problem shape (fixed by dataset): B=2, S=2048, A=16, H=1024, NH=16, HD=64
#define BB 2
#define SS 2048
#define AA 16
#define HH 1024
#define NH 16
#define HD 64

// ---- scratch (device globals; no allocation allowed) ----
__device__ __align__(16) float g_agg[BB * HH];         // masked-mean aspect features
__device__ __align__(16) float g_q[BB * HH];           // q[b, o]
__device__ __align__(16) float g_v[BB * NH * HH];      // folded key weights v[b, h, i]
__device__ __align__(16) float g_scores[BB * NH * SS]; // s[b, h, k]
__device__ __align__(16) float g_m[BB * NH];           // per-(b,h) max
__device__ __align__(16) float g_iz[BB * NH];          // per-(b,h) 1/(z*NH)
__device__ __align__(16) float g_w[BB * SS];           // final per-key weights

// ---- mask dtype detection (sentence_mask[0][0..3] always true since len >= S/2) ----
__device__ __forceinline__ int detect_mode(const void* sm) {
    unsigned int w0 = *(const unsigned int*)sm;
    if (w0 == 0x01010101u) return 1;   // 1-byte bool
    if (w0 == 0x3F800000u) return 2;   // float32
    if (w0 == 0x3F803F80u) return 3;   // bf16
    return 0;                          // int32
}
__device__ __forceinline__ bool mask_at(const void* p, int idx, int mode) {
    switch (mode) {
        case 1:  return ((const unsigned char*)p)[idx] != 0;
        case 2:  return ((const float*)p)[idx] != 0.0f;
        case 3:  return ((const unsigned short*)p)[idx] != 0;
        default: return ((const int*)p)[idx] != 0;
    }
}

// ---- K1: masked mean over aspects -> g_agg[b][i].  grid BB, block 256. ----
__global__ void k_agg(const float* __restrict__ h2, const void* __restrict__ am,
                      const void* __restrict__ sm) {
    int b = blockIdx.x;
    int mode = detect_mode(sm);
    float cnt = 0.f;
#pragma unroll
    for (int a = 0; a < AA; a++) cnt += mask_at(am, b * AA + a, mode) ? 1.f : 0.f;
    float inv = 1.f / fmaxf(cnt, 1.f);
    for (int i = threadIdx.x; i < HH; i += 256) {
        float s = 0.f;
#pragma unroll
        for (int a = 0; a < AA; a++)
            if (mask_at(am, b * AA + a, mode)) s += h2[(b * AA + a) * HH + i];
        g_agg[b * HH + i] = s * inv;
    }
}

// ---- K2: q[b,o] = dot(Wq[o,:], agg[b]).  grid (BB, HH/8), 8 warps, warp-per-row. ----
__global__ void __launch_bounds__(256) k_q(const float* __restrict__ Wq) {
    int b = blockIdx.x;
    int warp = threadIdx.x >> 5, lane = threadIdx.x & 31;
    int o = blockIdx.y * 8 + warp;
    const float4* wrow = (const float4*)(Wq + (size_t)o * HH);
    const float4* ag = (const float4*)(g_agg + b * HH);
    float acc = 0.f;
#pragma unroll
    for (int j = 0; j < HH / 128; j++) {   // 8 float4 per lane
        float4 wv = wrow[lane + j * 32];
        float4 av = ag[lane + j * 32];
        acc += wv.x * av.x + wv.y * av.y + wv.z * av.z + wv.w * av.w;
    }
#pragma unroll
    for (int off = 16; off; off >>= 1) acc += __shfl_xor_sync(0xffffffffu, acc, off);
    if (lane == 0) g_q[b * HH + o] = acc;
}

// ---- K3: v[b,h,i] = sum_o q[b,h*64+o] * Wk[h*64+o, i].  grid (BB*NH, HH/256), 256 thr. ----
__global__ void __launch_bounds__(256) k_fold(const float* __restrict__ Wk) {
    int b = blockIdx.x >> 4;
    int h = blockIdx.x & 15;
    int i = blockIdx.y * 256 + threadIdx.x;
    __shared__ float qs[HD];
    if (threadIdx.x < HD) qs[threadIdx.x] = g_q[b * HH + h * HD + threadIdx.x];
    __syncthreads();
    float acc = 0.f;
#pragma unroll 8
    for (int o = 0; o < HD; o++)
        acc += qs[o] * Wk[(size_t)(h * HD + o) * HH + i];
    g_v[(b * NH + h) * HH + i] = acc;
}

// ---- K4: scores[b,h,k] = 0.125 * dot(v[b,h,:], h1[b,k,:]) ----
// KT=2: 8 warps x 2 k = 16 k per block; grid (BB, 128) = 256 blocks, 2 blocks/SM.
// v[b] (64KB) staged in dynamic smem; float4 LDG/LDS throughout.
#define KT 2
extern __shared__ float vsh[];
__global__ void __launch_bounds__(256, 2) k_scores(const float* __restrict__ h1) {
    int b = blockIdx.x;
    int t = threadIdx.x;
    const float4* vb = (const float4*)(g_v + (size_t)b * NH * HH);
    float4* vs4 = (float4*)vsh;
    for (int j = t; j < NH * HH / 4; j += 256) vs4[j] = vb[j];
    __syncthreads();

    int warp = t >> 5, lane = t & 31;
    int k0 = blockIdx.y * 16 + warp * KT;

    const float4* r0 = (const float4*)(h1 + (size_t)(b * SS + k0 + 0) * HH);
    const float4* r1 = (const float4*)(h1 + (size_t)(b * SS + k0 + 1) * HH);

    float acc[NH][KT];
#pragma unroll
    for (int h = 0; h < NH; h++)
#pragma unroll
        for (int j = 0; j < KT; j++) acc[h][j] = 0.f;

#pragma unroll 2
    for (int m = 0; m < HH / 128; m++) {   // 8 iterations, 128 floats (32 float4) each
        int idx = lane + m * 32;
        float4 x0 = r0[idx], x1 = r1[idx];
#pragma unroll
        for (int h = 0; h < NH; h++) {
            float4 v = vs4[h * (HH / 4) + idx];
            acc[h][0] += v.x * x0.x + v.y * x0.y + v.z * x0.z + v.w * x0.w;
            acc[h][1] += v.x * x1.x + v.y * x1.y + v.z * x1.z + v.w * x1.w;
        }
    }
#pragma unroll
    for (int h = 0; h < NH; h++)
#pragma unroll
        for (int j = 0; j < KT; j++) {
            float s = acc[h][j];
#pragma unroll
            for (int off = 16; off; off >>= 1) s += __shfl_xor_sync(0xffffffffu, s, off);
            acc[h][j] = s;
        }
    if (lane < NH) {
        int h = lane;
#pragma unroll
        for (int j = 0; j < KT; j++)
            g_scores[(size_t)(b * NH + h) * SS + k0 + j] = acc[h][j] * 0.125f;
    }
}

// ---- K5: per-(b,h) masked max + sum-of-exp.  grid BB*NH, block 256. ----
__global__ void __launch_bounds__(256) k_reduce(const void* __restrict__ sm) {
    int b = blockIdx.x >> 4;
    int h = blockIdx.x & 15;
    int mode = detect_mode(sm);
    int t = threadIdx.x, warp = t >> 5, lane = t & 31;
    const float* srow = g_scores + (size_t)(b * NH + h) * SS;
    __shared__ float red[8];

    float mx = -1e30f;
    for (int k = t; k < SS; k += 256)
        if (mask_at(sm, b * SS + k, mode)) mx = fmaxf(mx, srow[k]);
#pragma unroll
    for (int off = 16; off; off >>= 1) mx = fmaxf(mx, __shfl_xor_sync(0xffffffffu, mx, off));
    if (lane == 0) red[warp] = mx;
    __syncthreads();
    mx = red[lane & 7];
#pragma unroll
    for (int off = 4; off; off >>= 1) mx = fmaxf(mx, __shfl_xor_sync(0xffffffffu, mx, off));
    mx = __shfl_sync(0xffffffffu, mx, 0);
    __syncthreads();

    float z = 0.f;
    for (int k = t; k < SS; k += 256)
        if (mask_at(sm, b * SS + k, mode)) z += __expf(srow[k] - mx);
#pragma unroll
    for (int off = 16; off; off >>= 1) z += __shfl_xor_sync(0xffffffffu, z, off);
    if (lane == 0) red[warp] = z;
    __syncthreads();
    if (t == 0) {
        float zz = 0.f;
#pragma unroll
        for (int wj = 0; wj < 8; wj++) zz += red[wj];
        g_m[b * NH + h] = mx;
        g_iz[b * NH + h] = 1.f / (zz * (float)NH);
    }
}

// ---- K6: w[b,k] = sum_h exp(s[b,h,k]-m[b,h]) * iz[b,h]  (0 if masked out). grid 8, 512 thr. ----
__global__ void __launch_bounds__(512) k_w(const void* __restrict__ sm) {
    int gid = blockIdx.x * 512 + threadIdx.x;   // 0 .. B*S-1
    int b = gid >> 11;
    int k = gid & (SS - 1);
    int mode = detect_mode(sm);
    float wv = 0.f;
    if (mask_at(sm, b * SS + k, mode)) {
#pragma unroll
        for (int h = 0; h < NH; h++) {
            float s = g_scores[(size_t)(b * NH + h) * SS + k];
            wv += __expf(s - g_m[b * NH + h]) * g_iz[b * NH + h];
        }
    }
    g_w[gid] = wv;
}

// ---- K7: broadcast w[b,:] to all S query rows.  grid B*S, 512 thr, float4. ----
__global__ void __launch_bounds__(512) k_bcast(float* __restrict__ out) {
    int row = blockIdx.x;          // b*S + q
    int b = row >> 11;
    float4 v = ((const float4*)(g_w + b * SS))[threadIdx.x];
    ((float4*)(out + (size_t)row * SS))[threadIdx.x] = v;
}

extern "C" void kernel_launch(void* const* d_in, const int* in_sizes, int n_in,
                              void* d_out, int out_size) {
    const float* h1 = (const float*)d_in[0];   // [B,S,H]
    const float* h2 = (const float*)d_in[1];   // [B,A,H]
    const void*  sm = d_in[2];                 // [B,S]
    const void*  am = d_in[3];                 // [B,A]
    const float* Wq = (const float*)d_in[4];   // [H,H]
    const float* Wk = (const float*)d_in[5];   // [H,H]
    float* out = (float*)d_out;                // [B,S,S]

    k_agg<<<BB, 256>>>(h2, am, sm);
    k_q<<<dim3(BB, HH / 8), 256>>>(Wq);
    k_fold<<<dim3(BB * NH, HH / 256), 256>>>(Wk);

    cudaFuncSetAttribute(k_scores, cudaFuncAttributeMaxDynamicSharedMemorySize,
                         NH * HH * (int)sizeof(float));
    k_scores<<<dim3(BB, 128), 256, NH * HH * sizeof(float)>>>(h1);

    k_reduce<<<BB * NH, 256>>>(sm);
    k_w<<<(BB * SS) / 512, 512>>>(sm);
    k_bcast<<<BB * SS, 512>>>(out);
}